// round 6
// baseline (speedup 1.0000x reference)
#include <cuda_runtime.h>

// SoftDTW forward, B=128, N=M=512, gamma=1.
// S = exp(-R):  S[i][j] = exp(-D[i][j]) * (S[i-1][j-1] + S[i-1][j] + S[i][j-1])
// Final: R = -(ln S + Es*ln2), warp-uniform power-of-2 rescaling every 64 steps.
//
// One CTA per batch, 4 warps:
//   warps 0-2: producers — stream D (ldcs, prefetch 2 phases deep), compute exp(-D),
//              stage into a 44-slot smem ring (slot (r+l)%44 for consumer-lane l's
//              16-col chunk) plus a per-chunk E8 = e8*...*e15 sidecar array.
//   warp 3:    consumer — wavefront DP, lane l owns cols [16l,16l+16), step s does
//              row i=s-l. One shfl_up per step. Steady steps use an early-forward
//              shortcut: h15 = E8*c7 + Horner(p8..p15), cutting the cross-lane
//              period from shfl+16FMA to shfl+9FMA.

namespace {
constexpr int BATCH   = 128;
constexpr int NR      = 512;
constexpr int MC      = 512;
constexpr int KP      = 6;                       // steps/rows per phase
constexpr int RS      = 44;                      // ring slots (write front +42 max)
constexpr int LSTRIDE = 36;                      // words/lane chunk; conflict-free LDS.128
constexpr int SLOTW   = 32 * LSTRIDE;            // 1152 words per slot
constexpr int ESM_OFF = RS * SLOTW;              // word offset of E8 sidecar
constexpr int SMEM_BYTES = (RS * SLOTW + RS * 32) * 4;  // 202752 + 5632 = 208384
constexpr int STEPS   = NR + 31;                 // 543
constexpr int NPHASE  = (STEPS + KP - 1) / KP;   // 91
constexpr unsigned FULL = 0xffffffffu;
}

__device__ __forceinline__ float4 exp4neg(float4 v) {
    float4 r;
    r.x = __expf(-v.x); r.y = __expf(-v.y);
    r.z = __expf(-v.z); r.w = __expf(-v.w);
    return r;
}

__global__ __launch_bounds__(128, 1)
void softdtw_fwd(const float* __restrict__ D, float* __restrict__ out) {
    extern __shared__ float sm[];
    const int b   = blockIdx.x;
    const int tid = threadIdx.x;
    const int w   = tid >> 5;
    const int l   = tid & 31;
    const float* __restrict__ G = D + (size_t)b * NR * MC + l * 16;

    if (w < 3) {
        // ---------------- producers (warps 0,1,2) ----------------
        float* lane_base = sm + l * LSTRIDE;
        float* esm       = sm + ESM_OFF + l;

        auto load2 = [&](int r0, float4 a[8]) {   // rows r0, r0+1
            const float4* s0 = (const float4*)(G + (size_t)r0 * MC);
            const float4* s1 = (const float4*)(G + (size_t)(r0 + 1) * MC);
            a[0] = __ldcs(s0 + 0); a[1] = __ldcs(s0 + 1);
            a[2] = __ldcs(s0 + 2); a[3] = __ldcs(s0 + 3);
            a[4] = __ldcs(s1 + 0); a[5] = __ldcs(s1 + 1);
            a[6] = __ldcs(s1 + 2); a[7] = __ldcs(s1 + 3);
        };
        auto store_row = [&](int r, const float4 a[4]) {
            const float4 e0 = exp4neg(a[0]), e1 = exp4neg(a[1]);
            const float4 e2 = exp4neg(a[2]), e3 = exp4neg(a[3]);
            const int slot = (r + l) % RS;
            float4* dst = (float4*)(lane_base + slot * SLOTW);
            dst[0] = e0; dst[1] = e1; dst[2] = e2; dst[3] = e3;
            esm[slot * 32] = ((e2.x * e2.y) * (e2.z * e2.w)) *
                             ((e3.x * e3.y) * (e3.z * e3.w));
        };

        // block k = rows [6k, 6k+6); this producer owns rows 6k+2w, 6k+2w+1.
        {   // block 0 written before the first barrier
            float4 T[8];
            load2(2 * w, T);
            store_row(2 * w,     T);
            store_row(2 * w + 1, T + 4);
        }
        float4 Rg[2][8];                 // block k lives in Rg[k & 1]
        load2(6  + 2 * w, Rg[1]);        // block 1
        load2(12 + 2 * w, Rg[0]);        // block 2

        for (int t = 0; t < NPHASE; ++t) {
            __syncthreads();
            const int kb = t + 1;
            const int r0 = 6 * kb + 2 * w;
            float4* buf = Rg[kb & 1];
            if (r0 < NR) {               // r0 even => r0+1 valid iff r0 valid
                store_row(r0,     buf);
                store_row(r0 + 1, buf + 4);
            }
            const int rf = 6 * (t + 3) + 2 * w;   // (t+3)&1 == kb&1: reuse buf
            if (rf < NR) load2(rf, buf);
        }
    } else {
        // ---------------- consumer (warp 3) ----------------
        float h[16];
        #pragma unroll
        for (int j = 0; j < 16; ++j) h[j] = 0.f;
        float xd = (l == 0) ? 1.f : 0.f;   // diag carry; virtual corner S[-1][-1]=1
        int   Es = 0;
        int   slot = 0;
        const float* lane_base = sm + l * LSTRIDE;
        const float* esm       = sm + ESM_OFF + l;

        auto rescale = [&]() {             // warp-uniform power-of-2 renormalize
            float m = h[0];
            #pragma unroll
            for (int j = 1; j < 16; ++j) m = fmaxf(m, h[j]);
            #pragma unroll
            for (int o = 16; o; o >>= 1)
                m = fmaxf(m, __shfl_xor_sync(FULL, m, o));
            if (m > 0.f) {
                const int   k = (__float_as_int(m) >> 23) - 127;
                const float f = __int_as_float((127 - k) << 23);
                #pragma unroll
                for (int j = 0; j < 16; ++j) h[j] *= f;
                xd *= f;
                Es += k;
            }
        };

        for (int t = 0; t < NPHASE; ++t) {
            __syncthreads();
            if (t >= 6 && t < 84) {
                // ---- steady: all lanes active (31 <= s < 504), no guards ----
                #pragma unroll
                for (int q = 0; q < KP; ++q) {
                    const int s = t * KP + q;
                    const float4* eb = (const float4*)(lane_base + slot * SLOTW);
                    const float4 E0 = eb[0], E1 = eb[1], E2 = eb[2], E3 = eb[3];
                    const float E8s = esm[slot * 32];
                    const float e[16] = { E0.x, E0.y, E0.z, E0.w,
                                          E1.x, E1.y, E1.z, E1.w,
                                          E2.x, E2.y, E2.z, E2.w,
                                          E3.x, E3.y, E3.z, E3.w };
                    const float xr = __shfl_up_sync(FULL, h[15], 1);
                    const float xl = (l == 0) ? 0.f : xr;

                    float p[16];
                    p[0] = e[0] * (xd + h[0]);
                    #pragma unroll
                    for (int j = 1; j < 16; ++j) p[j] = e[j] * (h[j - 1] + h[j]);

                    // off-path fold of the upper half
                    float qv = p[8];
                    #pragma unroll
                    for (int j = 9; j < 16; ++j) qv = fmaf(qv, e[j], p[j]);

                    // on-path: 8 FMAs to c7, then early h15
                    float c = xl;
                    #pragma unroll
                    for (int j = 0; j < 8; ++j) { c = fmaf(e[j], c, p[j]); h[j] = c; }
                    const float h15n = fmaf(E8s, c, qv);
                    #pragma unroll
                    for (int j = 8; j < 15; ++j) { c = fmaf(e[j], c, p[j]); h[j] = c; }
                    h[15] = h15n;
                    xd = xl;
                    slot = (slot + 1 == RS) ? 0 : slot + 1;
                    if ((s & 63) == 32) rescale();
                }
            } else {
                // ---- guarded head/tail ----
                #pragma unroll
                for (int q = 0; q < KP; ++q) {
                    const int s = t * KP + q;
                    if (s < STEPS) {
                        const float4* eb = (const float4*)(lane_base + slot * SLOTW);
                        const float4 E0 = eb[0], E1 = eb[1], E2 = eb[2], E3 = eb[3];
                        const float e[16] = { E0.x, E0.y, E0.z, E0.w,
                                              E1.x, E1.y, E1.z, E1.w,
                                              E2.x, E2.y, E2.z, E2.w,
                                              E3.x, E3.y, E3.z, E3.w };
                        const float xr = __shfl_up_sync(FULL, h[15], 1);
                        const float xl = (l == 0) ? 0.f : xr;
                        const bool act = (unsigned)(s - l) < (unsigned)NR;

                        float p[16];
                        p[0] = e[0] * (xd + h[0]);
                        #pragma unroll
                        for (int j = 1; j < 16; ++j) p[j] = e[j] * (h[j - 1] + h[j]);

                        float c = xl;
                        #pragma unroll
                        for (int j = 0; j < 16; ++j) {
                            c = fmaf(e[j], c, p[j]);
                            h[j] = act ? c : h[j];
                        }
                        xd = xl;
                        slot = (slot + 1 == RS) ? 0 : slot + 1;
                        if ((s & 63) == 32) rescale();
                    }
                }
            }
        }
        // cell (511,511): lane 31, step 542 -> h[15]
        if (l == 31)
            out[b] = -(logf(h[15]) + (float)Es * 0.69314718055994531f);
    }
}

extern "C" void kernel_launch(void* const* d_in, const int* in_sizes, int n_in,
                              void* d_out, int out_size) {
    (void)in_sizes; (void)n_in; (void)out_size;
    const float* D = (const float*)d_in[0];
    float* o       = (float*)d_out;
    cudaFuncSetAttribute(softdtw_fwd, cudaFuncAttributeMaxDynamicSharedMemorySize, SMEM_BYTES);
    softdtw_fwd<<<BATCH, 128, SMEM_BYTES>>>(D, o);
}

// round 7
// speedup vs baseline: 1.6080x; 1.6080x over previous
#include <cuda_runtime.h>

// SoftDTW forward, B=128, N=M=512, gamma=1.
// S = exp(-R):  S[i][j] = exp(-D[i][j]) * (S[i-1][j-1] + S[i-1][j] + S[i][j-1])
// Final: R = -(ln S + Es*ln2), warp-uniform power-of-2 rescaling every 5 phases.
//
// One CTA per batch, 4 warps:
//   warps 0-2 (SMSP 0-2): producers — stream D with loads issued a full phase
//              before use (ping-pong reg buffers), compute exp(-D), stage into a
//              44-slot smem ring, diagonal placement (row r, lane l) -> slot (r+l)%44.
//   warp 3 (SMSP 3): consumer — wavefront DP, lane l owns cols [16l,16l+16), step s
//              processes row i=s-l; one shfl_up per step; steady-region body has no
//              guards and prefetches the next step's e-values ahead of the FMA chain.

namespace {
constexpr int BATCH   = 128;
constexpr int NR      = 512;
constexpr int MC      = 512;
constexpr int KP      = 6;                       // steps/rows per phase
constexpr int RS      = 44;                      // ring slots
constexpr int LSTRIDE = 36;                      // words per lane chunk; conflict-free LDS.128
constexpr int SLOTW   = 32 * LSTRIDE;            // 1152 words per slot
constexpr int SMEM_BYTES = RS * SLOTW * 4;       // 202752
constexpr int STEPS   = NR + 31;                 // 543
constexpr int NPHASE  = (STEPS + KP - 1) / KP;   // 91
constexpr unsigned FULL = 0xffffffffu;
}

__device__ __forceinline__ float4 exp4neg(float4 v) {
    float4 r;
    r.x = __expf(-v.x); r.y = __expf(-v.y);
    r.z = __expf(-v.z); r.w = __expf(-v.w);
    return r;
}

__global__ __launch_bounds__(128, 1)
void softdtw_fwd(const float* __restrict__ D, float* __restrict__ out) {
    extern __shared__ float sm[];
    const int b   = blockIdx.x;
    const int tid = threadIdx.x;
    const int w   = tid >> 5;
    const int l   = tid & 31;
    const float* __restrict__ G = D + (size_t)b * NR * MC + l * 16;

    if (w < 3) {
        // ---------------- producers (warps 0,1,2) ----------------
        float* lane_base = sm + l * LSTRIDE;

        auto load2 = [&](int r0, float4 a[8]) {      // rows r0, r0+1
            const float4* s0 = (const float4*)(G + (size_t)r0 * MC);
            const float4* s1 = (const float4*)(G + (size_t)(r0 + 1) * MC);
            a[0] = s0[0]; a[1] = s0[1]; a[2] = s0[2]; a[3] = s0[3];
            a[4] = s1[0]; a[5] = s1[1]; a[6] = s1[2]; a[7] = s1[3];
        };
        auto store_row = [&](int r, const float4 a[4]) {
            float4* dst = (float4*)(lane_base + ((r + l) % RS) * SLOTW);
            dst[0] = exp4neg(a[0]); dst[1] = exp4neg(a[1]);
            dst[2] = exp4neg(a[2]); dst[3] = exp4neg(a[3]);
        };
        auto store2 = [&](int r0, const float4 a[8]) {
            store_row(r0, a);
            store_row(r0 + 1, a + 4);
        };

        // block k = rows [6k, 6k+6); this producer owns rows 6k+2w, 6k+2w+1.
        {   // block 0 written before the first barrier
            float4 T[8];
            load2(2 * w, T);
            store2(2 * w, T);
        }
        float4 X[8], Y[8];
        load2(KP + 2 * w, X);                        // block 1

        int t = 0;
        for (; t + 1 < NPHASE; t += 2) {
            __syncthreads();
            {   // phase t: load block t+2 FIRST (full-phase lead), then store block t+1
                const int rf = KP * (t + 2) + 2 * w;
                if (rf < NR) load2(rf, Y);
                const int r0 = KP * (t + 1) + 2 * w;
                if (r0 < NR) store2(r0, X);
            }
            __syncthreads();
            {   // phase t+1
                const int rf = KP * (t + 3) + 2 * w;
                if (rf < NR) load2(rf, X);
                const int r0 = KP * (t + 2) + 2 * w;
                if (r0 < NR) store2(r0, Y);
            }
        }
        if (t < NPHASE) __syncthreads();             // final odd phase (no rows left)
    } else {
        // ---------------- consumer (warp 3) ----------------
        float h[16];
        #pragma unroll
        for (int j = 0; j < 16; ++j) h[j] = 0.f;
        float xd = (l == 0) ? 1.f : 0.f;   // diag carry; virtual corner S[-1][-1] = 1
        int   Es = 0;
        int   slot = 0;
        const float* lane_base = sm + l * LSTRIDE;

        auto rescale = [&]() {             // warp-uniform power-of-2 renormalize
            float m = h[0];
            #pragma unroll
            for (int j = 1; j < 16; ++j) m = fmaxf(m, h[j]);
            #pragma unroll
            for (int o = 16; o; o >>= 1)
                m = fmaxf(m, __shfl_xor_sync(FULL, m, o));
            if (m > 0.f) {
                const int   k = (__float_as_int(m) >> 23) - 127;
                const float f = __int_as_float((127 - k) << 23);
                #pragma unroll
                for (int j = 0; j < 16; ++j) h[j] *= f;
                xd *= f;
                Es += k;
            }
        };

        for (int t = 0; t < NPHASE; ++t) {
            __syncthreads();
            if (t >= 6 && t < 84) {
                // ---- steady: steps 36..503, every lane active, no guards ----
                const float4* eb = (const float4*)(lane_base + slot * SLOTW);
                float4 C0 = eb[0], C1 = eb[1], C2 = eb[2], C3 = eb[3];
                #pragma unroll
                for (int q = 0; q < KP; ++q) {
                    const int nslot = (slot + 1 == RS) ? 0 : slot + 1;
                    float4 N0, N1, N2, N3;
                    if (q < KP - 1) {       // prefetch next step's e-values
                        const float4* nb = (const float4*)(lane_base + nslot * SLOTW);
                        N0 = nb[0]; N1 = nb[1]; N2 = nb[2]; N3 = nb[3];
                    }
                    const float e[16] = { C0.x, C0.y, C0.z, C0.w,
                                          C1.x, C1.y, C1.z, C1.w,
                                          C2.x, C2.y, C2.z, C2.w,
                                          C3.x, C3.y, C3.z, C3.w };
                    const float xr = __shfl_up_sync(FULL, h[15], 1);
                    const float xl = (l == 0) ? 0.f : xr;

                    float p[16];
                    p[0] = e[0] * (xd + h[0]);
                    #pragma unroll
                    for (int j = 1; j < 16; ++j) p[j] = e[j] * (h[j - 1] + h[j]);

                    float c = xl;
                    #pragma unroll
                    for (int j = 0; j < 16; ++j) { c = fmaf(e[j], c, p[j]); h[j] = c; }

                    xd = xl;
                    slot = nslot;
                    if (q < KP - 1) { C0 = N0; C1 = N1; C2 = N2; C3 = N3; }
                }
            } else {
                // ---- guarded head/tail ----
                #pragma unroll
                for (int q = 0; q < KP; ++q) {
                    const int s = t * KP + q;
                    if (s < STEPS) {
                        const float4* eb = (const float4*)(lane_base + slot * SLOTW);
                        const float4 E0 = eb[0], E1 = eb[1], E2 = eb[2], E3 = eb[3];
                        const float e[16] = { E0.x, E0.y, E0.z, E0.w,
                                              E1.x, E1.y, E1.z, E1.w,
                                              E2.x, E2.y, E2.z, E2.w,
                                              E3.x, E3.y, E3.z, E3.w };
                        const float xr = __shfl_up_sync(FULL, h[15], 1);
                        const float xl = (l == 0) ? 0.f : xr;
                        const bool act = (unsigned)(s - l) < (unsigned)NR;

                        float p[16];
                        p[0] = e[0] * (xd + h[0]);
                        #pragma unroll
                        for (int j = 1; j < 16; ++j) p[j] = e[j] * (h[j - 1] + h[j]);

                        float c = xl;
                        #pragma unroll
                        for (int j = 0; j < 16; ++j) {
                            c = fmaf(e[j], c, p[j]);
                            h[j] = act ? c : h[j];
                        }
                        xd = xl;
                        slot = (slot + 1 == RS) ? 0 : slot + 1;
                    }
                }
            }
            if ((t % 5) == 4) rescale();   // every 30 steps: growth <= 3^30, safe
        }
        // cell (511,511): lane 31, step 542 -> h[15]
        if (l == 31)
            out[b] = -(logf(h[15]) + (float)Es * 0.69314718055994531f);
    }
}

extern "C" void kernel_launch(void* const* d_in, const int* in_sizes, int n_in,
                              void* d_out, int out_size) {
    (void)in_sizes; (void)n_in; (void)out_size;
    const float* D = (const float*)d_in[0];
    float* o       = (float*)d_out;
    cudaFuncSetAttribute(softdtw_fwd, cudaFuncAttributeMaxDynamicSharedMemorySize, SMEM_BYTES);
    softdtw_fwd<<<BATCH, 128, SMEM_BYTES>>>(D, o);
}

// round 10
// speedup vs baseline: 1.9472x; 1.2110x over previous
#include <cuda_runtime.h>

// SoftDTW forward, B=128, N=M=512, gamma=1.
// S = exp(-R):  S[i][j] = exp(-D[i][j]) * (S[i-1][j-1] + S[i-1][j] + S[i][j-1])
// Final: R = -(ln S + Es*ln2), warp-uniform power-of-2 rescaling every 5 phases.
//
// One CTA per batch, 4 warps. TWO ROWS PER STEP:
//   lane l at step s computes rows 2(s-l), 2(s-l)+1 of its 16 columns [16l,16l+16).
//   287 steps total (vs 543 single-row). Neighbor data = lane l-1's h15 at three
//   half-step times (o15/m15/h15 registers), fetched with 3 shfl_up per step.
//   warps 0-2: producers — 4 rows/phase each, ping-pong reg buffers (load block
//              t+2 before storing block t+1), exp(-D) into a 44-slot smem ring;
//              slot (rp+l)%44 holds row-pair rp (2x16 floats) for consumer lane l.
//   warp 3:    consumer — 6 steps (12 rows) per phase, one barrier per phase.

namespace {
constexpr int BATCH   = 128;
constexpr int NR      = 512;
constexpr int MC      = 512;
constexpr int NRP     = 256;                     // row pairs
constexpr int KP      = 6;                       // steps (row-pairs) per phase
constexpr int RS      = 44;                      // ring slots
constexpr int LSTRIDE = 36;                      // words per lane chunk (32 used + pad)
constexpr int SLOTW   = 32 * LSTRIDE;            // 1152 words per slot
constexpr int SMEM_BYTES = RS * SLOTW * 4;       // 202752
constexpr int STEPS   = NRP + 31;                // 287
constexpr int NPHASE  = (STEPS + KP - 1) / KP;   // 48 (even)
constexpr unsigned FULL = 0xffffffffu;
}

__device__ __forceinline__ float4 exp4neg(float4 v) {
    float4 r;
    r.x = __expf(-v.x); r.y = __expf(-v.y);
    r.z = __expf(-v.z); r.w = __expf(-v.w);
    return r;
}

__global__ __launch_bounds__(128, 1)
void softdtw_fwd(const float* __restrict__ D, float* __restrict__ out) {
    extern __shared__ float sm[];
    const int b   = blockIdx.x;
    const int tid = threadIdx.x;
    const int w   = tid >> 5;
    const int l   = tid & 31;
    const float* __restrict__ G = D + (size_t)b * NR * MC + l * 16;

    if (w < 3) {
        // ---------------- producers (warps 0,1,2) ----------------
        float* lane_base = sm + l * LSTRIDE;

        auto load4 = [&](int r0, float4 a[16]) {         // rows r0..r0+3
            #pragma unroll
            for (int rr = 0; rr < 4; ++rr) {
                const float4* s = (const float4*)(G + (size_t)(r0 + rr) * MC);
                a[rr * 4 + 0] = s[0]; a[rr * 4 + 1] = s[1];
                a[rr * 4 + 2] = s[2]; a[rr * 4 + 3] = s[3];
            }
        };
        auto store_pair = [&](int rp, const float4 a[8]) {  // rows 2rp, 2rp+1
            float4* dst = (float4*)(lane_base + ((rp + l) % RS) * SLOTW);
            #pragma unroll
            for (int c = 0; c < 8; ++c) dst[c] = exp4neg(a[c]);
        };
        auto store_block = [&](int rp0, const float4 a[16]) {
            store_pair(rp0,     a);
            store_pair(rp0 + 1, a + 8);
        };

        // phase-block k supplies row-pairs [6k, 6k+6); this warp owns rp0 = 6k+2w.
        {   // block 0 before the first barrier
            float4 T[16];
            load4(4 * w, T);
            store_block(2 * w, T);
        }
        float4 X[16], Y[16];
        load4(12 + 4 * w, X);                            // block 1

        for (int t = 0; t + 1 < NPHASE; t += 2) {
            __syncthreads();
            {   // phase t: load block t+2 first (full-phase lead), store block t+1
                const int rf = 12 * (t + 2) + 4 * w;
                if (rf < NR) load4(rf, Y);
                const int rp0 = 6 * (t + 1) + 2 * w;
                if (rp0 + 1 < NRP) store_block(rp0, X);
            }
            __syncthreads();
            {   // phase t+1
                const int rf = 12 * (t + 3) + 4 * w;
                if (rf < NR) load4(rf, X);
                const int rp0 = 6 * (t + 2) + 2 * w;
                if (rp0 + 1 < NRP) store_block(rp0, Y);
            }
        }
    } else {
        // ---------------- consumer (warp 3) ----------------
        float h[16];
        #pragma unroll
        for (int j = 0; j < 16; ++j) h[j] = 0.f;
        float o15 = 0.f;   // h15 two half-steps back: S[2rp-1][16l+15] pre-step
        float m15 = 0.f;   // mid-step h15:            S[2rp  ][16l+15]
        int   Es = 0;
        int   slot = 0;
        const float* lane_base = sm + l * LSTRIDE;

        auto rescale = [&]() {
            float m = h[0];
            #pragma unroll
            for (int j = 1; j < 16; ++j) m = fmaxf(m, h[j]);
            #pragma unroll
            for (int o = 16; o; o >>= 1)
                m = fmaxf(m, __shfl_xor_sync(FULL, m, o));
            if (m > 0.f) {
                const int   k = (__float_as_int(m) >> 23) - 127;
                const float f = __int_as_float((127 - k) << 23);
                #pragma unroll
                for (int j = 0; j < 16; ++j) h[j] *= f;
                o15 *= f; m15 *= f;
                Es += k;
            }
        };

        for (int t = 0; t < NPHASE; ++t) {
            __syncthreads();
            if (t >= 6 && t <= 41) {
                // ---- steady: steps 36..251, every lane active ----
                #pragma unroll
                for (int q = 0; q < KP; ++q) {
                    const float4* eb = (const float4*)(lane_base + slot * SLOTW);
                    const float4 A0 = eb[0], A1 = eb[1], A2 = eb[2], A3 = eb[3];
                    const float4 B0 = eb[4], B1 = eb[5], B2 = eb[6], B3 = eb[7];
                    float z0 = __shfl_up_sync(FULL, o15, 1);   // diag row a
                    float z1 = __shfl_up_sync(FULL, m15, 1);   // left a / diag b
                    float z2 = __shfl_up_sync(FULL, h[15], 1); // left row b
                    if (l == 0) { z0 = 0.f; z1 = 0.f; z2 = 0.f; }

                    const float ea[16] = { A0.x, A0.y, A0.z, A0.w,
                                           A1.x, A1.y, A1.z, A1.w,
                                           A2.x, A2.y, A2.z, A2.w,
                                           A3.x, A3.y, A3.z, A3.w };
                    const float ebv[16] = { B0.x, B0.y, B0.z, B0.w,
                                            B1.x, B1.y, B1.z, B1.w,
                                            B2.x, B2.y, B2.z, B2.w,
                                            B3.x, B3.y, B3.z, B3.w };
                    // row a
                    float pa[16];
                    pa[0] = ea[0] * (z0 + h[0]);
                    #pragma unroll
                    for (int j = 1; j < 16; ++j) pa[j] = ea[j] * (h[j - 1] + h[j]);
                    float av[16];
                    float c = z1;
                    #pragma unroll
                    for (int j = 0; j < 16; ++j) { c = fmaf(ea[j], c, pa[j]); av[j] = c; }
                    // row b
                    float pb[16];
                    pb[0] = ebv[0] * (z1 + av[0]);
                    #pragma unroll
                    for (int j = 1; j < 16; ++j) pb[j] = ebv[j] * (av[j - 1] + av[j]);
                    o15 = h[15];
                    m15 = av[15];
                    float d = z2;
                    #pragma unroll
                    for (int j = 0; j < 16; ++j) { d = fmaf(ebv[j], d, pb[j]); h[j] = d; }

                    slot = (slot + 1 == RS) ? 0 : slot + 1;
                }
            } else {
                // ---- guarded head/tail ----
                #pragma unroll
                for (int q = 0; q < KP; ++q) {
                    const int s = t * KP + q;
                    if (s < STEPS) {
                        const float4* eb = (const float4*)(lane_base + slot * SLOTW);
                        const float4 A0 = eb[0], A1 = eb[1], A2 = eb[2], A3 = eb[3];
                        const float4 B0 = eb[4], B1 = eb[5], B2 = eb[6], B3 = eb[7];
                        float z0 = __shfl_up_sync(FULL, o15, 1);
                        float z1 = __shfl_up_sync(FULL, m15, 1);
                        float z2 = __shfl_up_sync(FULL, h[15], 1);
                        if (l == 0) {
                            z0 = (s == 0) ? 1.f : 0.f;   // virtual corner S[-1][-1]=1
                            z1 = 0.f; z2 = 0.f;
                        }
                        const bool act = (unsigned)(s - l) < (unsigned)NRP;

                        const float ea[16] = { A0.x, A0.y, A0.z, A0.w,
                                               A1.x, A1.y, A1.z, A1.w,
                                               A2.x, A2.y, A2.z, A2.w,
                                               A3.x, A3.y, A3.z, A3.w };
                        const float ebv[16] = { B0.x, B0.y, B0.z, B0.w,
                                                B1.x, B1.y, B1.z, B1.w,
                                                B2.x, B2.y, B2.z, B2.w,
                                                B3.x, B3.y, B3.z, B3.w };
                        float pa[16];
                        pa[0] = ea[0] * (z0 + h[0]);
                        #pragma unroll
                        for (int j = 1; j < 16; ++j) pa[j] = ea[j] * (h[j - 1] + h[j]);
                        float av[16];
                        float c = z1;
                        #pragma unroll
                        for (int j = 0; j < 16; ++j) { c = fmaf(ea[j], c, pa[j]); av[j] = c; }
                        float pb[16];
                        pb[0] = ebv[0] * (z1 + av[0]);
                        #pragma unroll
                        for (int j = 1; j < 16; ++j) pb[j] = ebv[j] * (av[j - 1] + av[j]);
                        const float o15n = h[15];
                        float d = z2;
                        #pragma unroll
                        for (int j = 0; j < 16; ++j) {
                            d = fmaf(ebv[j], d, pb[j]);
                            h[j] = act ? d : h[j];
                        }
                        o15 = act ? o15n   : o15;
                        m15 = act ? av[15] : m15;

                        slot = (slot + 1 == RS) ? 0 : slot + 1;
                    }
                }
            }
            if ((t % 5) == 4) rescale();   // every 30 steps: growth <= 9^30 < 2^127
        }
        // cell (511,511): lane 31, step 286, row b -> h[15]
        if (l == 31)
            out[b] = -(logf(h[15]) + (float)Es * 0.69314718055994531f);
    }
}

extern "C" void kernel_launch(void* const* d_in, const int* in_sizes, int n_in,
                              void* d_out, int out_size) {
    (void)in_sizes; (void)n_in; (void)out_size;
    const float* D = (const float*)d_in[0];
    float* o       = (float*)d_out;
    cudaFuncSetAttribute(softdtw_fwd, cudaFuncAttributeMaxDynamicSharedMemorySize, SMEM_BYTES);
    softdtw_fwd<<<BATCH, 128, SMEM_BYTES>>>(D, o);
}